// round 4
// baseline (speedup 1.0000x reference)
#include <cuda_runtime.h>
#include <cuda_bf16.h>
#include <math.h>
#include <stdint.h>

// Problem constants
#define T    4096
#define D    2048
#define E    8
#define H    704
#define KSEL 2
#define P    (T*KSEL)        // 8192 pairs
#define TM   128             // token tile
#define NT   72              // max token tiles: 8192/128 + 8 pad tiles
#define PMAX (NT*TM)         // 9216

#define BUFSZ 65536
#define SMEM_BYTES (1024 + 2*BUFSZ)   // 132096

// ---------------- device scratch ---------------------------------------------
__device__ float g_scores[P];
__device__ int   g_topi[P];
__device__ int   g_pair[PMAX];
__device__ int   g_off[E + 1];
__device__ __nv_bfloat16 g_xhi[(size_t)T * D];
__device__ __nv_bfloat16 g_xlo[(size_t)T * D];
__device__ __nv_bfloat16 g_wgt_hi[(size_t)E * H * D];  // [E][H][D]
__device__ __nv_bfloat16 g_wgt_lo[(size_t)E * H * D];
__device__ __nv_bfloat16 g_wut_hi[(size_t)E * H * D];
__device__ __nv_bfloat16 g_wut_lo[(size_t)E * H * D];
__device__ __nv_bfloat16 g_wdt_hi[(size_t)E * D * H];  // [E][D][H]
__device__ __nv_bfloat16 g_wdt_lo[(size_t)E * D * H];
__device__ __nv_bfloat16 g_hhi[(size_t)PMAX * H];
__device__ __nv_bfloat16 g_hlo[(size_t)PMAX * H];
__device__ float g_yp[(size_t)P * D];

// ---------------- PTX helpers ------------------------------------------------
__device__ __forceinline__ uint32_t smem_u32(const void* p) {
    uint32_t a;
    asm("{ .reg .u64 t; cvta.to.shared.u64 t, %1; cvt.u32.u64 %0, t; }" : "=r"(a) : "l"(p));
    return a;
}
__device__ __forceinline__ void cp16(uint32_t dst, const void* src, int sz) {
    asm volatile("cp.async.cg.shared.global [%0], [%1], 16, %2;"
                 :: "r"(dst), "l"(src), "r"(sz) : "memory");
}
#define CP_COMMIT() asm volatile("cp.async.commit_group;" ::: "memory")
#define CP_WAIT1()  asm volatile("cp.async.wait_group 1;" ::: "memory")
#define CP_WAIT0()  asm volatile("cp.async.wait_group 0;" ::: "memory")

__device__ __forceinline__ void ldsm4(uint32_t* r, uint32_t addr) {
    asm volatile("ldmatrix.sync.aligned.m8n8.x4.shared.b16 {%0,%1,%2,%3}, [%4];"
                 : "=r"(r[0]), "=r"(r[1]), "=r"(r[2]), "=r"(r[3]) : "r"(addr));
}
__device__ __forceinline__ void ldsm2(uint32_t* r, uint32_t addr) {
    asm volatile("ldmatrix.sync.aligned.m8n8.x2.shared.b16 {%0,%1}, [%2];"
                 : "=r"(r[0]), "=r"(r[1]) : "r"(addr));
}
__device__ __forceinline__ void mma16816(float* d, const uint32_t* a, const uint32_t* b) {
    asm volatile(
        "mma.sync.aligned.m16n8k16.row.col.f32.bf16.bf16.f32 "
        "{%0,%1,%2,%3},{%4,%5,%6,%7},{%8,%9},{%0,%1,%2,%3};\n"
        : "+f"(d[0]), "+f"(d[1]), "+f"(d[2]), "+f"(d[3])
        : "r"(a[0]), "r"(a[1]), "r"(a[2]), "r"(a[3]), "r"(b[0]), "r"(b[1]));
}

// ---------------- prep kernels ------------------------------------------------
__global__ void convert_x_kernel(const float* __restrict__ x) {
    size_t i = (size_t)blockIdx.x * 256 + threadIdx.x;   // over T*D/4
    float4 v = ((const float4*)x)[i];
    float f[4] = {v.x, v.y, v.z, v.w};
    __nv_bfloat16 hi[4], lo[4];
#pragma unroll
    for (int j = 0; j < 4; j++) {
        hi[j] = __float2bfloat16(f[j]);
        lo[j] = __float2bfloat16(f[j] - __bfloat162float(hi[j]));
    }
    __nv_bfloat162* ph = (__nv_bfloat162*)g_xhi + i * 2;
    __nv_bfloat162* pl = (__nv_bfloat162*)g_xlo + i * 2;
    ph[0] = __halves2bfloat162(hi[0], hi[1]); ph[1] = __halves2bfloat162(hi[2], hi[3]);
    pl[0] = __halves2bfloat162(lo[0], lo[1]); pl[1] = __halves2bfloat162(lo[2], lo[3]);
}

// in [E][R][C] fp32 -> out [E][C][R] bf16 hi/lo
__global__ void transpose_cv_kernel(const float* __restrict__ in,
                                    __nv_bfloat16* __restrict__ ohi,
                                    __nv_bfloat16* __restrict__ olo,
                                    int R, int C) {
    __shared__ float t[32][33];
    int e = blockIdx.z;
    const float* src = in + (size_t)e * R * C;
    int c0 = blockIdx.x * 32, r0 = blockIdx.y * 32;
#pragma unroll
    for (int i = threadIdx.y; i < 32; i += 8)
        t[i][threadIdx.x] = src[(size_t)(r0 + i) * C + c0 + threadIdx.x];
    __syncthreads();
    size_t obase = (size_t)e * R * C;
#pragma unroll
    for (int i = threadIdx.y; i < 32; i += 8) {
        float v = t[threadIdx.x][i];
        __nv_bfloat16 hi = __float2bfloat16(v);
        __nv_bfloat16 lo = __float2bfloat16(v - __bfloat162float(hi));
        size_t o = obase + (size_t)(c0 + i) * R + r0 + threadIdx.x;
        ohi[o] = hi; olo[o] = lo;
    }
}

// ---------------- gating ------------------------------------------------------
__global__ void gate_kernel(const float* __restrict__ x,
                            const float* __restrict__ Wg1,
                            const float* __restrict__ Wg2) {
    int warp = threadIdx.x >> 5, lane = threadIdx.x & 31;
    int t = blockIdx.x * 8 + warp;
    if (t >= T) return;
    const float* xr = x + (size_t)t * D;
    float acc[E];
#pragma unroll
    for (int e = 0; e < E; e++) acc[e] = 0.f;
    for (int d = lane; d < D; d += 32) {
        float xv = xr[d];
        const float4* w = (const float4*)(Wg1 + (size_t)d * E);
        float4 w0 = w[0], w1 = w[1];
        acc[0] += xv * w0.x; acc[1] += xv * w0.y; acc[2] += xv * w0.z; acc[3] += xv * w0.w;
        acc[4] += xv * w1.x; acc[5] += xv * w1.y; acc[6] += xv * w1.z; acc[7] += xv * w1.w;
    }
#pragma unroll
    for (int off = 16; off >= 1; off >>= 1)
#pragma unroll
        for (int e = 0; e < E; e++) acc[e] += __shfl_xor_sync(0xffffffffu, acc[e], off);
    if (lane == 0) {
        float a[E], lg[E];
#pragma unroll
        for (int e = 0; e < E; e++) a[e] = tanhf(acc[e]);
#pragma unroll
        for (int j = 0; j < E; j++) {
            float s = 0.f;
#pragma unroll
            for (int e = 0; e < E; e++) s += a[e] * Wg2[e * E + j];
            lg[j] = s;
        }
        int i0 = 0;
#pragma unroll
        for (int j = 1; j < E; j++) if (lg[j] > lg[i0]) i0 = j;
        int i1 = -1;
#pragma unroll
        for (int j = 0; j < E; j++) if (j != i0 && (i1 < 0 || lg[j] > lg[i1])) i1 = j;
        float ev = expf(lg[i1] - lg[i0]);
        float denom = 1.f + ev;
        g_topi[t * 2 + 0] = i0;  g_scores[t * 2 + 0] = 1.f / denom;
        g_topi[t * 2 + 1] = i1;  g_scores[t * 2 + 1] = ev / denom;
    }
}

// ---------------- routing + balance loss --------------------------------------
__global__ void route_kernel(float* __restrict__ d_out, long long out_n) {
    __shared__ float s_imp[256 * E];
    __shared__ float s_cnt[256 * E];
    __shared__ int   s_off[E + 1];
    __shared__ int   s_cur[E];
    int tid = threadIdx.x;
    float imp[E], cnt[E];
#pragma unroll
    for (int e = 0; e < E; e++) { imp[e] = 0.f; cnt[e] = 0.f; }
    for (int i = tid; i < P; i += 256) {
        int e = g_topi[i];
        imp[e] += g_scores[i];
        cnt[e] += 1.f;
    }
#pragma unroll
    for (int e = 0; e < E; e++) { s_imp[tid * E + e] = imp[e]; s_cnt[tid * E + e] = cnt[e]; }
    __syncthreads();
    for (int s = 128; s > 0; s >>= 1) {
        if (tid < s)
#pragma unroll
            for (int e = 0; e < E; e++) {
                s_imp[tid * E + e] += s_imp[(tid + s) * E + e];
                s_cnt[tid * E + e] += s_cnt[(tid + s) * E + e];
            }
        __syncthreads();
    }
    if (tid == 0) {
        int off = 0;
        for (int e = 0; e < E; e++) {
            s_off[e] = off; g_off[e] = off;
            int c = (int)s_cnt[e];
            off += ((c + TM - 1) / TM) * TM;
        }
        s_off[E] = off; g_off[E] = off;
        float mi = 0.f, ml = 0.f;
        for (int e = 0; e < E; e++) { mi += s_imp[e]; ml += s_cnt[e]; }
        mi /= E; ml /= E;
        float vi = 0.f, vl = 0.f;
        for (int e = 0; e < E; e++) {
            float di = s_imp[e] - mi; vi += di * di;
            float dl = s_cnt[e] - ml; vl += dl * dl;
        }
        vi /= (E - 1); vl /= (E - 1);
        float loss = 0.01f * (vi / (mi * mi + 1e-10f) + vl / (ml * ml + 1e-10f));
        if (out_n == (long long)T * D + 1) d_out[(size_t)T * D] = loss;
    }
    __syncthreads();
    for (int i = tid; i < PMAX; i += 256) g_pair[i] = -1;
    if (tid < E) s_cur[tid] = s_off[tid];
    __syncthreads();
    for (int i = tid; i < P; i += 256) {
        int e = g_topi[i];
        int p = atomicAdd(&s_cur[e], 1);
        g_pair[p] = i;
    }
}

// ======================= phase A: h = silu(x@Wg)*(x@Wu) =======================
// BM=128, BN=64 (H tile), BK=64. 8 warps: wy=wid>>1 (m: 32), wx=wid&1 (n: 32).
// smem buffer: Ahi 0, Alo 16K, Gh 32K, Gl 40K, Uh 48K, Ul 56K   (64 KB)
__global__ void __launch_bounds__(256, 1) mma_gu_kernel() {
    extern __shared__ char smem[];
    const int tid = threadIdx.x, wid = tid >> 5, lane = tid & 31;
    const int wy = wid >> 1, wx = wid & 1;
    int total = g_off[E];
    int tile0 = blockIdx.x * TM;
    if (tile0 >= total) return;
    int e = E - 1;
#pragma unroll
    for (int q = 0; q < E; q++) if (tile0 < g_off[q + 1]) { e = q; break; }
    const int h0 = blockIdx.y * 64;
    int* sp = (int*)smem;
    if (tid < TM) sp[tid] = g_pair[tile0 + tid];
    __syncthreads();
    uint32_t sb = smem_u32(smem);
    const size_t wbase = (size_t)e * H * D;

    // per-lane ldmatrix address precompute
    const uint32_t lc2 = (uint32_t)(lane >> 4) * 16;           // A k-halve byte off
    uint32_t aoff[2], axor[2];
#pragma unroll
    for (int mt = 0; mt < 2; mt++) {
        int r = wy * 32 + mt * 16 + (lane & 15);
        aoff[mt] = (uint32_t)r * 128; axor[mt] = (uint32_t)(r & 7) << 4;
    }
    const uint32_t bc2 = (uint32_t)((lane >> 3) & 1) * 16;     // B k-halve
    uint32_t boff[4], bxor[4];
#pragma unroll
    for (int nt = 0; nt < 4; nt++) {
        int r = wx * 32 + nt * 8 + (lane & 7);
        boff[nt] = (uint32_t)r * 128; bxor[nt] = (uint32_t)(r & 7) << 4;
    }

    float aG[2][4][4], aU[2][4][4];
#pragma unroll
    for (int mt = 0; mt < 2; mt++)
#pragma unroll
        for (int nt = 0; nt < 4; nt++)
#pragma unroll
            for (int j = 0; j < 4; j++) { aG[mt][nt][j] = 0.f; aU[mt][nt][j] = 0.f; }

    auto stage = [&](int c) {
        uint32_t bu = sb + 1024 + (uint32_t)(c & 1) * BUFSZ;
        int k0 = c * 64;
#pragma unroll
        for (int i = 0; i < 4; i++) {
            int idx = tid + i * 256, row = idx >> 3, seg = idx & 7;
            uint32_t so = (uint32_t)row * 128 + (((uint32_t)seg * 16) ^ (((uint32_t)row & 7) << 4));
            int ts = sp[row];
            int sz = (ts >= 0) ? 16 : 0;
            size_t off = (size_t)(ts >= 0 ? (ts >> 1) : 0) * D + k0 + seg * 8;
            cp16(bu + so,         g_xhi + off, sz);
            cp16(bu + 16384 + so, g_xlo + off, sz);
        }
#pragma unroll
        for (int i = 0; i < 2; i++) {
            int idx = tid + i * 256, row = idx >> 3, seg = idx & 7;
            uint32_t so = (uint32_t)row * 128 + (((uint32_t)seg * 16) ^ (((uint32_t)row & 7) << 4));
            size_t off = wbase + (size_t)(h0 + row) * D + k0 + seg * 8;
            cp16(bu + 32768 + so, g_wgt_hi + off, 16);
            cp16(bu + 40960 + so, g_wgt_lo + off, 16);
            cp16(bu + 49152 + so, g_wut_hi + off, 16);
            cp16(bu + 57344 + so, g_wut_lo + off, 16);
        }
        CP_COMMIT();
    };

    auto compute = [&](int b) {
        uint32_t bu = sb + 1024 + (uint32_t)b * BUFSZ;
        uint32_t Ah = bu, Al = bu + 16384, Gh = bu + 32768, Gl = bu + 40960,
                 Uh = bu + 49152, Ul = bu + 57344;
#pragma unroll
        for (int kq = 0; kq < 4; kq++) {
            uint32_t kk2 = (uint32_t)kq * 32;
            uint32_t ah[2][4], al[2][4];
#pragma unroll
            for (int mt = 0; mt < 2; mt++) {
                uint32_t o = aoff[mt] + ((kk2 + lc2) ^ axor[mt]);
                ldsm4(ah[mt], Ah + o);
                ldsm4(al[mt], Al + o);
            }
            uint32_t bgh[4][2], bgl[4][2], buh[4][2], bul[4][2];
#pragma unroll
            for (int nt = 0; nt < 4; nt++) {
                uint32_t o = boff[nt] + ((kk2 + bc2) ^ bxor[nt]);
                ldsm2(bgh[nt], Gh + o); ldsm2(bgl[nt], Gl + o);
                ldsm2(buh[nt], Uh + o); ldsm2(bul[nt], Ul + o);
            }
#pragma unroll
            for (int nt = 0; nt < 4; nt++)
#pragma unroll
                for (int mt = 0; mt < 2; mt++) {
                    mma16816(aG[mt][nt], ah[mt], bgh[nt]);
                    mma16816(aU[mt][nt], ah[mt], buh[nt]);
                }
#pragma unroll
            for (int nt = 0; nt < 4; nt++)
#pragma unroll
                for (int mt = 0; mt < 2; mt++) {
                    mma16816(aG[mt][nt], al[mt], bgh[nt]);
                    mma16816(aU[mt][nt], al[mt], buh[nt]);
                }
#pragma unroll
            for (int nt = 0; nt < 4; nt++)
#pragma unroll
                for (int mt = 0; mt < 2; mt++) {
                    mma16816(aG[mt][nt], ah[mt], bgl[nt]);
                    mma16816(aU[mt][nt], ah[mt], bul[nt]);
                }
        }
    };

    stage(0);
    for (int c = 0; c < 32; c++) {
        if (c < 31) { stage(c + 1); CP_WAIT1(); } else { CP_WAIT0(); }
        __syncthreads();
        compute(c & 1);
        __syncthreads();
    }

    // epilogue: silu(g)*u -> bf16 hi/lo, rows are sorted-pair indices
    int rl = lane >> 2;
    int cb = h0 + wx * 32 + (lane & 3) * 2;
#pragma unroll
    for (int mt = 0; mt < 2; mt++)
#pragma unroll
        for (int nt = 0; nt < 4; nt++) {
            int cc = cb + nt * 8;
#pragma unroll
            for (int half = 0; half < 2; half++) {
                int rr = tile0 + wy * 32 + mt * 16 + rl + half * 8;
                float g0 = aG[mt][nt][half * 2],     u0 = aU[mt][nt][half * 2];
                float g1 = aG[mt][nt][half * 2 + 1], u1 = aU[mt][nt][half * 2 + 1];
                float h0v = g0 / (1.f + __expf(-g0)) * u0;
                float h1v = g1 / (1.f + __expf(-g1)) * u1;
                __nv_bfloat16 b0 = __float2bfloat16(h0v);
                __nv_bfloat16 b1 = __float2bfloat16(h1v);
                __nv_bfloat16 l0 = __float2bfloat16(h0v - __bfloat162float(b0));
                __nv_bfloat16 l1 = __float2bfloat16(h1v - __bfloat162float(b1));
                *(__nv_bfloat162*)(g_hhi + (size_t)rr * H + cc) = __halves2bfloat162(b0, b1);
                *(__nv_bfloat162*)(g_hlo + (size_t)rr * H + cc) = __halves2bfloat162(l0, l1);
            }
        }
}

// ======================= phase B: yp = h @ Wdown ==============================
// BM=128, BN=128 (D tile), BK=64. 8 warps: wy (m:32), wx (n:64).
// smem buffer: Ahi 0, Alo 16K, Bh 32K(16K), Bl 48K    (64 KB)
__global__ void __launch_bounds__(256, 1) mma_down_kernel() {
    extern __shared__ char smem[];
    const int tid = threadIdx.x, wid = tid >> 5, lane = tid & 31;
    const int wy = wid >> 1, wx = wid & 1;
    int total = g_off[E];
    int tile0 = blockIdx.x * TM;
    if (tile0 >= total) return;
    int e = E - 1;
#pragma unroll
    for (int q = 0; q < E; q++) if (tile0 < g_off[q + 1]) { e = q; break; }
    const int d0 = blockIdx.y * 128;
    int* sp = (int*)smem;
    if (tid < TM) sp[tid] = g_pair[tile0 + tid];
    __syncthreads();
    uint32_t sb = smem_u32(smem);
    const size_t wbase = (size_t)e * D * H;

    const uint32_t lc2 = (uint32_t)(lane >> 4) * 16;
    uint32_t aoff[2], axor[2];
#pragma unroll
    for (int mt = 0; mt < 2; mt++) {
        int r = wy * 32 + mt * 16 + (lane & 15);
        aoff[mt] = (uint32_t)r * 128; axor[mt] = (uint32_t)(r & 7) << 4;
    }
    const uint32_t bc2 = (uint32_t)((lane >> 3) & 1) * 16;
    uint32_t boff[8], bxor[8];
#pragma unroll
    for (int nt = 0; nt < 8; nt++) {
        int r = wx * 64 + nt * 8 + (lane & 7);
        boff[nt] = (uint32_t)r * 128; bxor[nt] = (uint32_t)(r & 7) << 4;
    }

    float acc[2][8][4];
#pragma unroll
    for (int mt = 0; mt < 2; mt++)
#pragma unroll
        for (int nt = 0; nt < 8; nt++)
#pragma unroll
            for (int j = 0; j < 4; j++) acc[mt][nt][j] = 0.f;

    auto stage = [&](int c) {
        uint32_t bu = sb + 1024 + (uint32_t)(c & 1) * BUFSZ;
        int k0 = c * 64;
#pragma unroll
        for (int i = 0; i < 4; i++) {
            int idx = tid + i * 256, row = idx >> 3, seg = idx & 7;
            uint32_t so = (uint32_t)row * 128 + (((uint32_t)seg * 16) ^ (((uint32_t)row & 7) << 4));
            size_t off = (size_t)(tile0 + row) * H + k0 + seg * 8;
            cp16(bu + so,         g_hhi + off, 16);
            cp16(bu + 16384 + so, g_hlo + off, 16);
        }
#pragma unroll
        for (int i = 0; i < 4; i++) {
            int idx = tid + i * 256, row = idx >> 3, seg = idx & 7;
            uint32_t so = (uint32_t)row * 128 + (((uint32_t)seg * 16) ^ (((uint32_t)row & 7) << 4));
            size_t off = wbase + (size_t)(d0 + row) * H + k0 + seg * 8;
            cp16(bu + 32768 + so, g_wdt_hi + off, 16);
            cp16(bu + 49152 + so, g_wdt_lo + off, 16);
        }
        CP_COMMIT();
    };

    auto compute = [&](int b) {
        uint32_t bu = sb + 1024 + (uint32_t)b * BUFSZ;
        uint32_t Ah = bu, Al = bu + 16384, Bh = bu + 32768, Bl = bu + 49152;
#pragma unroll
        for (int kq = 0; kq < 4; kq++) {
            uint32_t kk2 = (uint32_t)kq * 32;
            uint32_t ah[2][4], al[2][4];
#pragma unroll
            for (int mt = 0; mt < 2; mt++) {
                uint32_t o = aoff[mt] + ((kk2 + lc2) ^ axor[mt]);
                ldsm4(ah[mt], Ah + o);
                ldsm4(al[mt], Al + o);
            }
            uint32_t bh[8][2], bl[8][2];
#pragma unroll
            for (int nt = 0; nt < 8; nt++) {
                uint32_t o = boff[nt] + ((kk2 + bc2) ^ bxor[nt]);
                ldsm2(bh[nt], Bh + o); ldsm2(bl[nt], Bl + o);
            }
#pragma unroll
            for (int nt = 0; nt < 8; nt++)
#pragma unroll
                for (int mt = 0; mt < 2; mt++) mma16816(acc[mt][nt], ah[mt], bh[nt]);
#pragma unroll
            for (int nt = 0; nt < 8; nt++)
#pragma unroll
                for (int mt = 0; mt < 2; mt++) mma16816(acc[mt][nt], al[mt], bh[nt]);
#pragma unroll
            for (int nt = 0; nt < 8; nt++)
#pragma unroll
                for (int mt = 0; mt < 2; mt++) mma16816(acc[mt][nt], ah[mt], bl[nt]);
        }
    };

    stage(0);
    for (int c = 0; c < 11; c++) {
        if (c < 10) { stage(c + 1); CP_WAIT1(); } else { CP_WAIT0(); }
        __syncthreads();
        compute(c & 1);
        __syncthreads();
    }

    // epilogue: scatter fp32 to g_yp per pair
    int rl = lane >> 2;
    int cb = d0 + wx * 64 + (lane & 3) * 2;
#pragma unroll
    for (int mt = 0; mt < 2; mt++) {
#pragma unroll
        for (int half = 0; half < 2; half++) {
            int m = wy * 32 + mt * 16 + rl + half * 8;
            int ts = sp[m];
            if (ts >= 0) {
                float* yrow = g_yp + (size_t)ts * D;
#pragma unroll
                for (int nt = 0; nt < 8; nt++) {
                    float2 v = { acc[mt][nt][half * 2], acc[mt][nt][half * 2 + 1] };
                    *(float2*)(yrow + cb + nt * 8) = v;
                }
            }
        }
    }
}

// ---------------- combine -----------------------------------------------------
__global__ void combine_kernel(float* __restrict__ y) {
    size_t i4 = (size_t)blockIdx.x * 256 + threadIdx.x;
    int t  = (int)(i4 >> 9);
    int c4 = (int)(i4 & 511);
    float s0 = g_scores[t * 2 + 0];
    float s1 = g_scores[t * 2 + 1];
    const float4* p0 = (const float4*)(g_yp + (size_t)(t * 2 + 0) * D);
    const float4* p1 = (const float4*)(g_yp + (size_t)(t * 2 + 1) * D);
    float4 a = p0[c4], b = p1[c4];
    float4 o;
    o.x = s0 * a.x + s1 * b.x;
    o.y = s0 * a.y + s1 * b.y;
    o.z = s0 * a.z + s1 * b.z;
    o.w = s0 * a.w + s1 * b.w;
    ((float4*)y)[i4] = o;
}

// ---------------- launch ------------------------------------------------------
extern "C" void kernel_launch(void* const* d_in, const int* in_sizes, int n_in,
                              void* d_out, int out_size) {
    const float* x     = (const float*)d_in[0];
    const float* Wg1   = (const float*)d_in[1];
    const float* Wg2   = (const float*)d_in[2];
    const float* Wgate = (const float*)d_in[3];
    const float* Wup   = (const float*)d_in[4];
    const float* Wdown = (const float*)d_in[5];
    float* out = (float*)d_out;

    cudaFuncSetAttribute(mma_gu_kernel,   cudaFuncAttributeMaxDynamicSharedMemorySize, SMEM_BYTES);
    cudaFuncSetAttribute(mma_down_kernel, cudaFuncAttributeMaxDynamicSharedMemorySize, SMEM_BYTES);

    convert_x_kernel<<<(unsigned)(((size_t)T * D / 4) / 256), 256>>>(x);

    __nv_bfloat16 *wgt_hi, *wgt_lo, *wut_hi, *wut_lo, *wdt_hi, *wdt_lo;
    cudaGetSymbolAddress((void**)&wgt_hi, g_wgt_hi);
    cudaGetSymbolAddress((void**)&wgt_lo, g_wgt_lo);
    cudaGetSymbolAddress((void**)&wut_hi, g_wut_hi);
    cudaGetSymbolAddress((void**)&wut_lo, g_wut_lo);
    cudaGetSymbolAddress((void**)&wdt_hi, g_wdt_hi);
    cudaGetSymbolAddress((void**)&wdt_lo, g_wdt_lo);

    dim3 tb(32, 8);
    transpose_cv_kernel<<<dim3(H / 32, D / 32, E), tb>>>(Wgate, wgt_hi, wgt_lo, D, H);
    transpose_cv_kernel<<<dim3(H / 32, D / 32, E), tb>>>(Wup,   wut_hi, wut_lo, D, H);
    transpose_cv_kernel<<<dim3(D / 32, H / 32, E), tb>>>(Wdown, wdt_hi, wdt_lo, H, D);

    gate_kernel<<<T / 8, 256>>>(x, Wg1, Wg2);
    route_kernel<<<1, 256>>>(out, (long long)out_size);

    mma_gu_kernel<<<dim3(NT, H / 64), 256, SMEM_BYTES>>>();
    mma_down_kernel<<<dim3(NT, D / 128), 256, SMEM_BYTES>>>();

    combine_kernel<<<(unsigned)(((size_t)T * D / 4) / 256), 256>>>(out);
}